// round 4
// baseline (speedup 1.0000x reference)
#include <cuda_runtime.h>
#include <math.h>

#define BB 16
#define HH 384
#define WW 384
#define NPIX (BB * HH * WW)
#define NWORDS 12               // 384 / 32
#define RPB 8                   // rows per block in kernel 1

// Scratch: horizontal nearest-fg distance g per pixel, uint16 (g <= 768).
__device__ __align__(16) unsigned short g_g[NPIX];

// ---------------------------------------------------------------------------
// Kernel 1: per-row 1D distance to nearest foreground pixel (exact).
// 384 threads, 8 rows/block. Load phase (2 passes): each thread loads int4
// (4 cols) and ORs a 4-bit nibble into a shared row bitmask. Compute phase:
// thread j finds nearest set bit via clz/ffs per row (word-scan fallback).
// No-fg row -> g = BIG = 768 (matches reference clip). Zeroes out[0].
// ---------------------------------------------------------------------------
__global__ void row_dist_kernel(const int* __restrict__ targets,
                                float* __restrict__ out) {
    __shared__ unsigned smask[RPB][NWORDS];
    const int tid = threadIdx.x;                    // 0..383
    const int row0 = blockIdx.x * RPB;

    if (blockIdx.x == 0 && tid == 0) out[0] = 0.0f;

    if (tid < RPB * NWORDS) ((unsigned*)smask)[tid] = 0u;
    __syncthreads();

    // Build fg bitmasks: 2 passes x (4 rows x 96 quads)
    #pragma unroll
    for (int p = 0; p < 2; ++p) {
        const int k = p * 4 + tid / 96;
        const int q = tid % 96;
        const int4 t4 = *(const int4*)(targets + (size_t)(row0 + k) * WW + q * 4);
        const unsigned nib = (unsigned)(t4.x != 0)
                           | ((unsigned)(t4.y != 0) << 1)
                           | ((unsigned)(t4.z != 0) << 2)
                           | ((unsigned)(t4.w != 0) << 3);
        if (nib) atomicOr(&smask[k][q >> 3], nib << ((q & 7) * 4));
    }
    __syncthreads();

    const int j = tid;
    const int wj = j >> 5;
    const int bj = j & 31;

    #pragma unroll
    for (int k = 0; k < RPB; ++k) {
        const unsigned* mask = smask[k];
        const unsigned own = mask[wj];

        int dl;
        const unsigned ml = own & (0xFFFFFFFFu >> (31 - bj));
        if (ml) {
            dl = bj - (31 - __clz(ml));
        } else {
            dl = 0x7FFFFF;
            for (int w = wj - 1; w >= 0; --w) {
                const unsigned m = mask[w];
                if (m) { dl = j - (w * 32 + 31 - __clz(m)); break; }
            }
        }

        int dr;
        const unsigned mr = own & (0xFFFFFFFFu << bj);
        if (mr) {
            dr = (__ffs(mr) - 1) - bj;
        } else {
            dr = 0x7FFFFF;
            for (int w = wj + 1; w < NWORDS; ++w) {
                const unsigned m = mask[w];
                if (m) { dr = (w * 32 + __ffs(m) - 1) - j; break; }
            }
        }

        int d = min(dl, dr);
        d = min(d, 768);                            // BIG = H + W (no-fg row)
        g_g[(size_t)(row0 + k) * WW + j] = (unsigned short)d;
    }
}

// ---------------------------------------------------------------------------
// Min-update of 8 bests from one uint4 (8 x u16 g) at squared row offset r2.
// ---------------------------------------------------------------------------
__device__ __forceinline__ void upd8(const uint4 u, const float r2, float* best) {
    const float a0 = (float)(u.x & 0xFFFFu), a1 = (float)(u.x >> 16);
    const float a2 = (float)(u.y & 0xFFFFu), a3 = (float)(u.y >> 16);
    const float a4 = (float)(u.z & 0xFFFFu), a5 = (float)(u.z >> 16);
    const float a6 = (float)(u.w & 0xFFFFu), a7 = (float)(u.w >> 16);
    best[0] = fminf(best[0], fmaf(a0, a0, r2));
    best[1] = fminf(best[1], fmaf(a1, a1, r2));
    best[2] = fminf(best[2], fmaf(a2, a2, r2));
    best[3] = fminf(best[3], fmaf(a3, a3, r2));
    best[4] = fminf(best[4], fmaf(a4, a4, r2));
    best[5] = fminf(best[5], fmaf(a5, a5, r2));
    best[6] = fminf(best[6], fmaf(a6, a6, r2));
    best[7] = fminf(best[7], fmaf(a7, a7, r2));
}

// ---------------------------------------------------------------------------
// Kernel 2: exact vertical lower-envelope min fused with sigmoid, |p-t|,
// sqrt, block reduction, scaled atomicAdd. 8 columns/thread.
//
// Branch-free unconditional prefix r=1..3 with CLAMPED row indices:
// reading row max(i-r,0) (resp. min(i+r,H-1)) instead of skipping is exact,
// because that row was already included at its true smaller offset, and
// r^2 + g^2 >= (i-row)^2 + g^2, so the extra min term never undershoots.
// With Bernoulli(0.5) targets, P(true dist > 3) ~ 2^-28, so the checked
// continuation loop (r >= 4) is essentially never entered; it preserves
// exactness for arbitrary inputs. t == 1 <=> g == 0 (targets not re-read).
// ---------------------------------------------------------------------------
__global__ void loss_kernel(const float* __restrict__ logits,
                            float* __restrict__ out) {
    const int tid = blockIdx.x * blockDim.x + threadIdx.x;   // < NPIX/8
    const int base = tid * 8;
    const int j = base % WW;                  // multiple of 8 -> 16B aligned
    const int i = (base / WW) % HH;
    const int b = base / (WW * HH);

    const unsigned short* gimg = g_g + (size_t)b * HH * WW;

    // Own row
    const uint4 ow = *(const uint4*)(gimg + i * WW + j);
    unsigned go[8];
    go[0] = ow.x & 0xFFFFu; go[1] = ow.x >> 16;
    go[2] = ow.y & 0xFFFFu; go[3] = ow.y >> 16;
    go[4] = ow.z & 0xFFFFu; go[5] = ow.z >> 16;
    go[6] = ow.w & 0xFFFFu; go[7] = ow.w >> 16;
    float best[8];
    #pragma unroll
    for (int k = 0; k < 8; ++k) {
        const float f = (float)go[k];
        best[k] = f * f;
    }

    // Unconditional prefix r = 1..3 (clamped, branch-free, full MLP)
    #pragma unroll
    for (int r = 1; r <= 3; ++r) {
        const int iu = max(i - r, 0);
        const int id = min(i + r, HH - 1);
        const uint4 u = *(const uint4*)(gimg + iu * WW + j);
        const uint4 v = *(const uint4*)(gimg + id * WW + j);
        const float r2 = (float)(r * r);
        upd8(u, r2, best);
        upd8(v, r2, best);
    }

    float bmax = best[0];
    #pragma unroll
    for (int k = 1; k < 8; ++k) bmax = fmaxf(bmax, best[k]);

    // Rare exact continuation (clamped rows remain safe)
    #pragma unroll 1
    for (int r = 4; ; ++r) {
        const float r2 = (float)(r * r);
        if (r2 >= bmax) break;
        const int iu = max(i - r, 0);
        const int id = min(i + r, HH - 1);
        const uint4 u = *(const uint4*)(gimg + iu * WW + j);
        const uint4 v = *(const uint4*)(gimg + id * WW + j);
        upd8(u, r2, best);
        upd8(v, r2, best);
        bmax = best[0];
        #pragma unroll
        for (int k = 1; k < 8; ++k) bmax = fmaxf(bmax, best[k]);
    }

    // Fused loss: sigmoid, |p - t|, * sqrt(d2)
    const float4 lg0 = *(const float4*)(logits + base);
    const float4 lg1 = *(const float4*)(logits + base + 4);
    float lx[8] = {lg0.x, lg0.y, lg0.z, lg0.w, lg1.x, lg1.y, lg1.z, lg1.w};

    float val = 0.0f;
    #pragma unroll
    for (int k = 0; k < 8; ++k) {
        const float p = 1.0f / (1.0f + __expf(-lx[k]));
        const float t = (go[k] == 0u) ? 1.0f : 0.0f;
        val += fabsf(p - t) * sqrtf(best[k]);
    }

    // Warp + block reduction, one scaled atomic per block
    #pragma unroll
    for (int off = 16; off > 0; off >>= 1)
        val += __shfl_xor_sync(0xFFFFFFFFu, val, off);

    __shared__ float warp_sums[8];                  // 256 threads = 8 warps
    const int lane = threadIdx.x & 31;
    const int wid = threadIdx.x >> 5;
    if (lane == 0) warp_sums[wid] = val;
    __syncthreads();
    if (wid == 0) {
        float s = (lane < (blockDim.x >> 5)) ? warp_sums[lane] : 0.0f;
        #pragma unroll
        for (int off = 4; off > 0; off >>= 1)
            s += __shfl_xor_sync(0xFFFFFFFFu, s, off);
        if (lane == 0) atomicAdd(out, s * (1.0f / (float)NPIX));
    }
}

extern "C" void kernel_launch(void* const* d_in, const int* in_sizes, int n_in,
                              void* d_out, int out_size) {
    const float* logits = (const float*)d_in[0];
    const int* targets = (const int*)d_in[1];
    float* out = (float*)d_out;

    (void)in_sizes; (void)n_in; (void)out_size;

    // 1) Horizontal distances (u16, bitmask-based) + out zeroing
    row_dist_kernel<<<(BB * HH) / RPB, WW>>>(targets, out);

    // 2) Vertical envelope + loss + reduction
    const int threads = 256;
    const int blocks = (NPIX / 8) / threads;        // 1152
    loss_kernel<<<blocks, threads>>>(logits, out);
}

// round 5
// speedup vs baseline: 1.1326x; 1.1326x over previous
#include <cuda_runtime.h>
#include <math.h>

#define BB 16
#define HH 384
#define WW 384
#define NPIX (BB * HH * WW)
#define NWORDS 12               // 384 / 32
#define RPB 4                   // rows per block in kernel 1

// Scratch: horizontal nearest-fg distance g per pixel, uint16 (g <= 768).
__device__ __align__(16) unsigned short g_g[NPIX];

// ---------------------------------------------------------------------------
// Kernel 1: per-row 1D distance to nearest foreground pixel (exact).
// 384 threads, 4 rows/block. Each thread loads int4 (4 cols) and ORs a 4-bit
// nibble into a shared row bitmask (12 words/row); thread j then finds the
// nearest set bit via clz/ffs (word-scan fallback exact). No-fg row -> g =
// BIG = 768 (matches reference clip). Zeroes out[0].
// ---------------------------------------------------------------------------
__global__ void row_dist_kernel(const int* __restrict__ targets,
                                float* __restrict__ out) {
    __shared__ unsigned smask[RPB][NWORDS];
    const int tid = threadIdx.x;                    // 0..383
    const int row0 = blockIdx.x * RPB;

    if (blockIdx.x == 0 && tid == 0) out[0] = 0.0f;

    if (tid < RPB * NWORDS) ((unsigned*)smask)[tid] = 0u;
    __syncthreads();

    // Build fg bitmasks: thread -> (row k, quad q) = cols 4q..4q+3
    {
        const int k = tid / 96;
        const int q = tid % 96;
        const int4 t4 = *(const int4*)(targets + (size_t)(row0 + k) * WW + q * 4);
        const unsigned nib = (unsigned)(t4.x != 0)
                           | ((unsigned)(t4.y != 0) << 1)
                           | ((unsigned)(t4.z != 0) << 2)
                           | ((unsigned)(t4.w != 0) << 3);
        if (nib) atomicOr(&smask[k][q >> 3], nib << ((q & 7) * 4));
    }
    __syncthreads();

    const int j = tid;
    const int wj = j >> 5;
    const int bj = j & 31;

    #pragma unroll
    for (int k = 0; k < RPB; ++k) {
        const unsigned* mask = smask[k];
        const unsigned own = mask[wj];

        int dl;
        const unsigned ml = own & (0xFFFFFFFFu >> (31 - bj));
        if (ml) {
            dl = bj - (31 - __clz(ml));
        } else {
            dl = 0x7FFFFF;
            for (int w = wj - 1; w >= 0; --w) {
                const unsigned m = mask[w];
                if (m) { dl = j - (w * 32 + 31 - __clz(m)); break; }
            }
        }

        int dr;
        const unsigned mr = own & (0xFFFFFFFFu << bj);
        if (mr) {
            dr = (__ffs(mr) - 1) - bj;
        } else {
            dr = 0x7FFFFF;
            for (int w = wj + 1; w < NWORDS; ++w) {
                const unsigned m = mask[w];
                if (m) { dr = (w * 32 + __ffs(m) - 1) - j; break; }
            }
        }

        int d = min(dl, dr);
        d = min(d, 768);                            // BIG = H + W (no-fg row)
        g_g[(size_t)(row0 + k) * WW + j] = (unsigned short)d;
    }
}

// Min-update of 4 bests from one uint2 (4 x u16 g) at squared offset r2.
__device__ __forceinline__ void upd4(const uint2 u, const float r2, float* best) {
    const float a0 = (float)(u.x & 0xFFFFu), a1 = (float)(u.x >> 16);
    const float a2 = (float)(u.y & 0xFFFFu), a3 = (float)(u.y >> 16);
    best[0] = fminf(best[0], fmaf(a0, a0, r2));
    best[1] = fminf(best[1], fmaf(a1, a1, r2));
    best[2] = fminf(best[2], fmaf(a2, a2, r2));
    best[3] = fminf(best[3], fmaf(a3, a3, r2));
}

// ---------------------------------------------------------------------------
// Kernel 2: exact vertical lower-envelope min fused with sigmoid, |p-t|,
// sqrt, block reduction, scaled atomicAdd. 4 columns/thread (32-reg budget).
//
// Unconditional CLAMPED prefix r=1,2: reading row max(i-r,0)/min(i+r,H-1)
// instead of skipping is exact (the clamped row was already included at its
// true smaller offset; r^2+g^2 can only overshoot). All 5 g-loads issue
// back-to-back (full MLP, no serial loop chain). P(d^2 >= 9) ~ 3e-8 per
// pixel, so the checked continuation loop from r=3 runs ~0 iterations;
// it preserves exactness regardless. t == 1 <=> g == 0 (targets not re-read).
// ---------------------------------------------------------------------------
__global__ void loss_kernel(const float* __restrict__ logits,
                            float* __restrict__ out) {
    const int tid = blockIdx.x * blockDim.x + threadIdx.x;   // < NPIX/4
    const int base = tid * 4;
    const int j = base % WW;                  // multiple of 4 -> 8B aligned
    const int i = (base / WW) % HH;
    const int b = base / (WW * HH);

    const unsigned short* gimg = g_g + (size_t)b * HH * WW + j;

    const int im1 = max(i - 1, 0), im2 = max(i - 2, 0);
    const int ip1 = min(i + 1, HH - 1), ip2 = min(i + 2, HH - 1);

    // 5 independent loads, issued together
    const uint2 ow = *(const uint2*)(gimg + i * WW);
    const uint2 u1 = *(const uint2*)(gimg + im1 * WW);
    const uint2 v1 = *(const uint2*)(gimg + ip1 * WW);
    const uint2 u2 = *(const uint2*)(gimg + im2 * WW);
    const uint2 v2 = *(const uint2*)(gimg + ip2 * WW);

    const unsigned go0 = ow.x & 0xFFFFu, go1 = ow.x >> 16;
    const unsigned go2 = ow.y & 0xFFFFu, go3 = ow.y >> 16;
    float best[4];
    {
        const float f0 = (float)go0, f1 = (float)go1;
        const float f2 = (float)go2, f3 = (float)go3;
        best[0] = f0 * f0; best[1] = f1 * f1;
        best[2] = f2 * f2; best[3] = f3 * f3;
    }
    upd4(u1, 1.0f, best);
    upd4(v1, 1.0f, best);
    upd4(u2, 4.0f, best);
    upd4(v2, 4.0f, best);

    float bmax = fmaxf(fmaxf(best[0], best[1]), fmaxf(best[2], best[3]));

    // Rare exact continuation (clamped rows remain safe; terminates by r=769)
    #pragma unroll 1
    for (int r = 3; ; ++r) {
        const float r2 = (float)(r * r);
        if (r2 >= bmax) break;
        const int iu = max(i - r, 0);
        const int id = min(i + r, HH - 1);
        const uint2 u = *(const uint2*)(gimg + iu * WW);
        const uint2 v = *(const uint2*)(gimg + id * WW);
        upd4(u, r2, best);
        upd4(v, r2, best);
        bmax = fmaxf(fmaxf(best[0], best[1]), fmaxf(best[2], best[3]));
    }

    // Fused loss: |sigmoid(x) - t| = 1/(1 + exp(t ? x : -x)),  t = (g==0)
    const float4 lg = *(const float4*)(logits + base);
    float val;
    {
        const float e0 = __expf((go0 == 0u) ? lg.x : -lg.x);
        const float e1 = __expf((go1 == 0u) ? lg.y : -lg.y);
        const float e2 = __expf((go2 == 0u) ? lg.z : -lg.z);
        const float e3 = __expf((go3 == 0u) ? lg.w : -lg.w);
        val  = __fdividef(sqrtf(best[0]), 1.0f + e0);
        val += __fdividef(sqrtf(best[1]), 1.0f + e1);
        val += __fdividef(sqrtf(best[2]), 1.0f + e2);
        val += __fdividef(sqrtf(best[3]), 1.0f + e3);
    }

    // Warp + block reduction, one scaled atomic per block
    #pragma unroll
    for (int off = 16; off > 0; off >>= 1)
        val += __shfl_xor_sync(0xFFFFFFFFu, val, off);

    __shared__ float warp_sums[8];                  // 256 threads = 8 warps
    const int lane = threadIdx.x & 31;
    const int wid = threadIdx.x >> 5;
    if (lane == 0) warp_sums[wid] = val;
    __syncthreads();
    if (wid == 0) {
        float s = (lane < (blockDim.x >> 5)) ? warp_sums[lane] : 0.0f;
        #pragma unroll
        for (int off = 4; off > 0; off >>= 1)
            s += __shfl_xor_sync(0xFFFFFFFFu, s, off);
        if (lane == 0) atomicAdd(out, s * (1.0f / (float)NPIX));
    }
}

extern "C" void kernel_launch(void* const* d_in, const int* in_sizes, int n_in,
                              void* d_out, int out_size) {
    const float* logits = (const float*)d_in[0];
    const int* targets = (const int*)d_in[1];
    float* out = (float*)d_out;

    (void)in_sizes; (void)n_in; (void)out_size;

    // 1) Horizontal distances (u16, bitmask-based) + out zeroing
    row_dist_kernel<<<(BB * HH) / RPB, WW>>>(targets, out);

    // 2) Vertical envelope + loss + reduction
    const int threads = 256;
    const int blocks = (NPIX / 4) / threads;        // 2304
    loss_kernel<<<blocks, threads>>>(logits, out);
}